// round 15
// baseline (speedup 1.0000x reference)
#include <cuda_runtime.h>
#include <cuda_bf16.h>
#include <math.h>
#include <stdint.h>

#define NB 4096
typedef unsigned long long u64;

// ================= mma.sync / ldmatrix helpers =================
__device__ __forceinline__ uint32_t smem_u32(const void* p) {
    uint32_t a;
    asm("{ .reg .u64 t; cvta.to.shared.u64 t, %1; cvt.u32.u64 %0, t; }" : "=r"(a) : "l"(p));
    return a;
}
__device__ __forceinline__ void ldsm_x4(uint32_t &r0, uint32_t &r1, uint32_t &r2, uint32_t &r3,
                                        uint32_t addr) {
    asm volatile("ldmatrix.sync.aligned.m8n8.x4.shared.b16 {%0,%1,%2,%3}, [%4];"
                 : "=r"(r0), "=r"(r1), "=r"(r2), "=r"(r3) : "r"(addr));
}
__device__ __forceinline__ void ldsm_x4t(uint32_t &r0, uint32_t &r1, uint32_t &r2, uint32_t &r3,
                                         uint32_t addr) {
    asm volatile("ldmatrix.sync.aligned.m8n8.x4.trans.shared.b16 {%0,%1,%2,%3}, [%4];"
                 : "=r"(r0), "=r"(r1), "=r"(r2), "=r"(r3) : "r"(addr));
}
__device__ __forceinline__ void mma16816(float* d, const uint32_t* a, uint32_t b0, uint32_t b1) {
    asm volatile(
        "mma.sync.aligned.m16n8k16.row.col.f32.bf16.bf16.f32 "
        "{%0,%1,%2,%3}, {%4,%5,%6,%7}, {%8,%9}, {%0,%1,%2,%3};"
        : "+f"(d[0]), "+f"(d[1]), "+f"(d[2]), "+f"(d[3])
        : "r"(a[0]), "r"(a[1]), "r"(a[2]), "r"(a[3]), "r"(b0), "r"(b1));
}
__device__ __forceinline__ uint32_t pkbf(float a, float b) {
    __nv_bfloat162 t(__float2bfloat16(a), __float2bfloat16(b));
    uint32_t r; asm("mov.b32 %0, %1;" : "=r"(r) : "r"(*(uint32_t*)&t)); return r;
}

// ================= scratch =================
__device__ float g_tw1t[25 * 32];        // conv1 SIGNS [tap][oc]
__device__ float g_alpha1[32];
__device__ float g_tw2t[800 * 64];       // conv2 SIGNS [ic*25+t][oc]
__device__ float g_alpha2[64];
__device__ float g_twf1[512 * 1024];     // fc1 SIGNS [oc][k]
__device__ float g_alphaf1[512];
__device__ float g_twf2[10 * 512];       // fc2 full tern values
__device__ __align__(16) __nv_bfloat16 g_w2bf[800 * 64];    // conv2 T bf16, k=(t*32+ic)
__device__ __align__(16) __nv_bfloat16 g_wf1bf[1024 * 512]; // fc1 T bf16 [k][oc]

__device__ float g_pool1pre[(size_t)NB * 32 * 144];  // pooled pre-BN conv1 [n][pos*32+ic]
__device__ float g_pool2pre[(size_t)NB * 1024];      // pooled pre-BN conv2 [n][oc*16+pos]
__device__ float g_fc1o[(size_t)NB * 512];

__device__ float g_ps1[NB * 32], g_pq1[NB * 32];
__device__ float g_ps2[(NB / 2) * 64], g_pq2[(NB / 2) * 64];
__device__ float g_bns1[32], g_bnb1[32];
__device__ float g_bns2[64], g_bnb2[64];

// ================= ternarize =================
__global__ void __launch_bounds__(256) k_ternarize_all(const float* __restrict__ w1,
                                                       const float* __restrict__ w2,
                                                       const float* __restrict__ wf1,
                                                       const float* __restrict__ wf2) {
    int b = blockIdx.x;
    const float* wc; int per, mode, ch;
    if (b < 32)       { ch = b;       wc = w1  + (size_t)ch * 25;   per = 25;   mode = 0; }
    else if (b < 96)  { ch = b - 32;  wc = w2  + (size_t)ch * 800;  per = 800;  mode = 1; }
    else if (b < 608) { ch = b - 96;  wc = wf1 + (size_t)ch * 1024; per = 1024; mode = 2; }
    else              { ch = b - 608; wc = wf2 + (size_t)ch * 512;  per = 512;  mode = 3; }

    int tid = threadIdx.x;
    __shared__ float sA[8], sB[8];
    __shared__ float s_delta, s_alpha;

    float s = 0.f;
    for (int i = tid; i < per; i += 256) s += fabsf(wc[i]);
    for (int o = 16; o; o >>= 1) s += __shfl_xor_sync(0xffffffffu, s, o);
    if ((tid & 31) == 0) sA[tid >> 5] = s;
    __syncthreads();
    if (tid == 0) {
        float t = 0.f;
        for (int i = 0; i < 8; i++) t += sA[i];
        s_delta = 0.7f * t / (float)per;
    }
    __syncthreads();
    float delta = s_delta;

    float sa = 0.f, cn = 0.f;
    for (int i = tid; i < per; i += 256) {
        float a = fabsf(wc[i]);
        if (a > delta) { sa += a; cn += 1.f; }
    }
    for (int o = 16; o; o >>= 1) {
        sa += __shfl_xor_sync(0xffffffffu, sa, o);
        cn += __shfl_xor_sync(0xffffffffu, cn, o);
    }
    __syncthreads();
    if ((tid & 31) == 0) { sA[tid >> 5] = sa; sB[tid >> 5] = cn; }
    __syncthreads();
    if (tid == 0) {
        float a = 0.f, c = 0.f;
        for (int i = 0; i < 8; i++) { a += sA[i]; c += sB[i]; }
        s_alpha = a / c;
    }
    __syncthreads();
    float alpha = s_alpha;
    if (tid == 0) {
        if (mode == 0) g_alpha1[ch] = alpha;
        if (mode == 1) g_alpha2[ch] = alpha;
        if (mode == 2) g_alphaf1[ch] = alpha;
    }
    for (int i = tid; i < per; i += 256) {
        float v = wc[i];
        bool on = fabsf(v) > delta;
        float sgn = on ? copysignf(1.f, v) : 0.f;
        if (mode == 0)      g_tw1t[i * 32 + ch] = sgn;
        else if (mode == 1) g_tw2t[i * 64 + ch] = sgn;
        else if (mode == 2) g_twf1[(size_t)ch * 1024 + i] = sgn;
        else                g_twf2[ch * 512 + i] = on ? copysignf(alpha, v) : 0.f;
    }
}

// ---- conv2 weight prep ----
__global__ void __launch_bounds__(256) k_prepw2() {
    int f = blockIdx.x * 256 + threadIdx.x;
    if (f >= 51200) return;
    int k = f >> 6, oc = f & 63;
    int t = k >> 5, ic = k & 31;
    g_w2bf[k * 64 + oc] = __float2bfloat16(g_tw2t[(ic * 25 + t) * 64 + oc]);
}

// ---- fc1 weight prep ----
__global__ void __launch_bounds__(256) k_prepwf1() {
    int f = blockIdx.x * 256 + threadIdx.x;
    if (f >= 524288) return;
    int k = f >> 9, oc = f & 511;
    g_wf1bf[(size_t)k * 512 + oc] = __float2bfloat16(g_twf1[(size_t)oc * 1024 + k]);
}

// ================= conv1 via mma.sync: staged aligned im2col =================
// 1 image/CTA, 288 threads (9 warps x 4 m16 tiles). M=576 pooled-quad-major,
// N=32 oc, K=32 (25 taps + 7 zero). A hi/lo bf16 planes, 80B rows. Exact ternary B.
#define OFF1_X 0
#define OFF1_AH 3200
#define OFF1_AL (OFF1_AH + 576 * 80)     // 49280
#define OFF1_B  (OFF1_AL + 576 * 80)     // 95360
#define OFF1_MISC (OFF1_B + 32 * 80)     // 97920
#define SMEM1 (OFF1_MISC + 2816)

extern "C" __global__ void __launch_bounds__(288) k_conv1_mma(const float* __restrict__ x,
                                                              const float* __restrict__ bias) {
    extern __shared__ __align__(16) uint8_t smem[];
    uint32_t sb = smem_u32(smem);
    int n = blockIdx.x, tid = threadIdx.x, wid = tid >> 5, lid = tid & 31;

    float* s_x = (float*)(smem + OFF1_X);
    float* s_alpha = (float*)(smem + OFF1_MISC);
    float* s_bias  = (float*)(smem + OFF1_MISC + 128);
    float* s_ps    = (float*)(smem + OFF1_MISC + 256);    // [9][32]
    float* s_pq    = (float*)(smem + OFF1_MISC + 1408);   // [9][32]

    if (tid < 32) { s_alpha[tid] = g_alpha1[tid]; s_bias[tid] = bias[tid]; }
    // load x image (784 f32)
    for (int i = tid; i < 196; i += 288)
        ((float4*)s_x)[i] = ((const float4*)(x + (size_t)n * 784))[i];
    // B: [32 k][40 bf16] rows, taps 0..24 real, 25..31 zero
    for (int i = tid; i < 640; i += 288) {
        int row = i / 20, c = i - (i / 20) * 20;
        float a = 0.f, b2 = 0.f;
        if (row < 25 && c < 16) {
            a = g_tw1t[row * 32 + c * 2];
            b2 = g_tw1t[row * 32 + c * 2 + 1];
        }
        ((uint32_t*)(smem + OFF1_B + row * 80))[c] = pkbf(a, b2);
    }
    __syncthreads();

    // build im2col A (hi/lo), pooled-quad-major rows; vectorized STS.128
    for (int m = tid; m < 576; m += 288) {
        int pp = m >> 2, q = m & 3;
        int oy = 2 * (pp / 12) + (q >> 1);
        int ox = 2 * (pp - (pp / 12) * 12) + (q & 1);
        float v[25];
#pragma unroll
        for (int ky = 0; ky < 5; ky++) {
            const float* xr = &s_x[(oy + ky) * 28 + ox];
#pragma unroll
            for (int kx = 0; kx < 5; kx++) v[ky * 5 + kx] = xr[kx];
        }
        uint32_t wh[16], wl[16];
#pragma unroll
        for (int t = 0; t < 12; t++) {
            float a = v[2 * t], b2 = v[2 * t + 1];
            __nv_bfloat16 ha = __float2bfloat16(a), hb = __float2bfloat16(b2);
            wh[t] = pkbf(a, b2);
            wl[t] = pkbf(a - __bfloat162float(ha), b2 - __bfloat162float(hb));
        }
        {
            float a = v[24];
            __nv_bfloat16 ha = __float2bfloat16(a);
            wh[12] = pkbf(a, 0.f);
            wl[12] = pkbf(a - __bfloat162float(ha), 0.f);
        }
#pragma unroll
        for (int t = 13; t < 16; t++) { wh[t] = 0u; wl[t] = 0u; }
        uint4* rh = (uint4*)(smem + OFF1_AH + m * 80);
        uint4* rl = (uint4*)(smem + OFF1_AL + m * 80);
#pragma unroll
        for (int t = 0; t < 4; t++) {
            rh[t] = make_uint4(wh[4 * t], wh[4 * t + 1], wh[4 * t + 2], wh[4 * t + 3]);
            rl[t] = make_uint4(wl[4 * t], wl[4 * t + 1], wl[4 * t + 2], wl[4 * t + 3]);
        }
    }
    __syncthreads();

    int rowoff8 = ((lid >> 3) & 1) * 8 + (lid & 7);
    int colb = (lid >= 16) ? 16 : 0;
    uint32_t sbAH = sb + OFF1_AH, sbAL = sb + OFF1_AL, sbB = sb + OFF1_B;

    // B fragments (load once): Bf[kstep][nb][4]
    uint32_t Bf[2][2][4];
#pragma unroll
    for (int ks = 0; ks < 2; ks++)
#pragma unroll
        for (int nb = 0; nb < 2; nb++)
            ldsm_x4t(Bf[ks][nb][0], Bf[ks][nb][1], Bf[ks][nb][2], Bf[ks][nb][3],
                     sbB + (uint32_t)((ks * 16 + rowoff8) * 80 + nb * 32 + colb));

    float biasv[8], alphav[8];
#pragma unroll
    for (int j = 0; j < 4; j++) {
        int c = j * 8 + (lid & 3) * 2;
        biasv[j * 2] = s_bias[c];         alphav[j * 2] = s_alpha[c];
        biasv[j * 2 + 1] = s_bias[c + 1]; alphav[j * 2 + 1] = s_alpha[c + 1];
    }
    float su[8] = {}, sq[8] = {};

#pragma unroll 1
    for (int t = wid * 4; t < wid * 4 + 4; t++) {
        float acc[4][4] = {};
#pragma unroll
        for (int ks = 0; ks < 2; ks++) {
            uint32_t ra = (uint32_t)((t * 16 + rowoff8) * 80 + colb + ks * 32);
            uint32_t aH[4], aL[4];
            ldsm_x4(aH[0], aH[1], aH[2], aH[3], sbAH + ra);
            ldsm_x4(aL[0], aL[1], aL[2], aL[3], sbAL + ra);
#pragma unroll
            for (int nb = 0; nb < 2; nb++) {
                mma16816(acc[nb * 2 + 0], aH, Bf[ks][nb][0], Bf[ks][nb][1]);
                mma16816(acc[nb * 2 + 1], aH, Bf[ks][nb][2], Bf[ks][nb][3]);
                mma16816(acc[nb * 2 + 0], aL, Bf[ks][nb][0], Bf[ks][nb][1]);
                mma16816(acc[nb * 2 + 1], aL, Bf[ks][nb][2], Bf[ks][nb][3]);
            }
        }
        // epilogue: alpha/bias, stats, pooled store
#pragma unroll
        for (int j = 0; j < 4; j++) {
            float v0 = acc[j][0] * alphav[j * 2] + biasv[j * 2];
            float v1 = acc[j][1] * alphav[j * 2 + 1] + biasv[j * 2 + 1];
            float v2 = acc[j][2] * alphav[j * 2] + biasv[j * 2];
            float v3 = acc[j][3] * alphav[j * 2 + 1] + biasv[j * 2 + 1];
            su[j * 2]     += v0 + v2;
            su[j * 2 + 1] += v1 + v3;
            sq[j * 2]     += v0 * v0 + v2 * v2;
            sq[j * 2 + 1] += v1 * v1 + v3 * v3;
            float m0 = v0, m1 = v1, m2 = v2, m3 = v3;
            m0 = fmaxf(m0, __shfl_xor_sync(0xffffffffu, m0, 4));
            m1 = fmaxf(m1, __shfl_xor_sync(0xffffffffu, m1, 4));
            m2 = fmaxf(m2, __shfl_xor_sync(0xffffffffu, m2, 4));
            m3 = fmaxf(m3, __shfl_xor_sync(0xffffffffu, m3, 4));
            m0 = fmaxf(m0, __shfl_xor_sync(0xffffffffu, m0, 8));
            m1 = fmaxf(m1, __shfl_xor_sync(0xffffffffu, m1, 8));
            m2 = fmaxf(m2, __shfl_xor_sync(0xffffffffu, m2, 8));
            m3 = fmaxf(m3, __shfl_xor_sync(0xffffffffu, m3, 8));
            if ((lid & 12) == 0) {
                int g = (lid >> 4);
                int pp0 = t * 4 + g;
                int pp2 = t * 4 + 2 + g;
                int col = j * 8 + (lid & 3) * 2;
                float* base = &g_pool1pre[(size_t)n * 4608];
                *(float2*)&base[pp0 * 32 + col] = make_float2(m0, m1);
                *(float2*)&base[pp2 * 32 + col] = make_float2(m2, m3);
            }
        }
    }
    // BN1 partials
#pragma unroll
    for (int c = 0; c < 8; c++) {
        for (int o = 4; o <= 16; o <<= 1) {
            su[c] += __shfl_xor_sync(0xffffffffu, su[c], o);
            sq[c] += __shfl_xor_sync(0xffffffffu, sq[c], o);
        }
    }
    if (lid < 4) {
#pragma unroll
        for (int j = 0; j < 4; j++) {
            int c = j * 8 + lid * 2;
            s_ps[wid * 32 + c] = su[j * 2];         s_pq[wid * 32 + c] = sq[j * 2];
            s_ps[wid * 32 + c + 1] = su[j * 2 + 1]; s_pq[wid * 32 + c + 1] = sq[j * 2 + 1];
        }
    }
    __syncthreads();
    if (tid < 32) {
        float a = 0.f, q2 = 0.f;
#pragma unroll
        for (int w = 0; w < 9; w++) { a += s_ps[w * 32 + tid]; q2 += s_pq[w * 32 + tid]; }
        g_ps1[n * 32 + tid] = a;
        g_pq1[n * 32 + tid] = q2;
    }
}

// ================= BN stats =================
__global__ void __launch_bounds__(256) k_bnstats(int which,
                                                 const float* __restrict__ gamma,
                                                 const float* __restrict__ beta) {
    const int C = (which == 1) ? 32 : 64;
    const int cnt = (which == 1) ? NB : (NB / 2);
    const float* ps = (which == 1) ? g_ps1 : g_ps2;
    const float* pq = (which == 1) ? g_pq1 : g_pq2;
    float* scale = (which == 1) ? g_bns1 : g_bns2;
    float* shift = (which == 1) ? g_bnb1 : g_bnb2;
    const float inv_count = (which == 1) ? (1.f / (4096.f * 576.f)) : (1.f / (4096.f * 64.f));

    int c = blockIdx.x, tid = threadIdx.x;
    __shared__ float sA[8], sB[8];
    float s = 0.f, q = 0.f;
    for (int i = tid; i < cnt; i += 256) { s += ps[i * C + c]; q += pq[i * C + c]; }
    for (int o = 16; o; o >>= 1) {
        s += __shfl_xor_sync(0xffffffffu, s, o);
        q += __shfl_xor_sync(0xffffffffu, q, o);
    }
    if ((tid & 31) == 0) { sA[tid >> 5] = s; sB[tid >> 5] = q; }
    __syncthreads();
    if (tid == 0) {
        float ts = 0.f, tq = 0.f;
        for (int i = 0; i < 8; i++) { ts += sA[i]; tq += sB[i]; }
        float mean = ts * inv_count;
        float var = tq * inv_count - mean * mean;
        float sc = gamma[c] * rsqrtf(var + 1e-5f);
        scale[c] = sc;
        shift[c] = beta[c] - mean * sc;
    }
}

// ================= conv2 via mma.sync (loader decodes [pos][ic]) =================
#define OFF_B 0
#define B_MAXROWS 416
#define OFF_XH (B_MAXROWS * 144)
#define OFF_XL (OFF_XH + 288 * 80)
#define OFF_MISC (OFF_XL + 288 * 80)
#define SMEM_MMA (OFF_MISC + 2048)

extern "C" __global__ void __launch_bounds__(256) k_conv2_mma(const float* __restrict__ bias) {
    extern __shared__ __align__(16) uint8_t smem[];
    uint32_t sb = smem_u32(smem);
    int tid = threadIdx.x, wid = tid >> 5, lid = tid & 31;
    int n0 = blockIdx.x * 2;

    float* s_bias  = (float*)(smem + OFF_MISC);
    float* s_alpha = (float*)(smem + OFF_MISC + 256);
    float* s_s1    = (float*)(smem + OFF_MISC + 512);
    float* s_h1    = (float*)(smem + OFF_MISC + 640);
    int*   s_koff  = (int*)(smem + OFF_MISC + 768);
    float* s_psum  = (float*)(smem + OFF_MISC + 1024);
    float* s_psq   = (float*)(smem + OFF_MISC + 1536);

    if (tid < 64) { s_bias[tid] = bias[tid]; s_alpha[tid] = g_alpha2[tid]; }
    if (tid < 32) { s_s1[tid] = g_bns1[tid]; s_h1[tid] = g_bnb1[tid]; }
    if (tid < 50) {
        int t = tid >> 1;
        s_koff[tid] = ((t / 5) * 12 + (t % 5)) * 80 + (tid & 1) * 32;
    }
    __syncthreads();

    __nv_bfloat16* xh = (__nv_bfloat16*)(smem + OFF_XH);
    __nv_bfloat16* xl = (__nv_bfloat16*)(smem + OFF_XL);
    for (int e = tid; e < 9216; e += 256) {
        int img = e / 4608, rem = e - img * 4608;
        int p = rem >> 5, ic = rem & 31;     // [pos][ic] layout from conv1_mma
        float v = g_pool1pre[(size_t)(n0 + img) * 4608 + rem];
        v = fmaxf(v * s_s1[ic] + s_h1[ic], 0.f);
        __nv_bfloat16 h = __float2bfloat16(v);
        __nv_bfloat16 l = __float2bfloat16(v - __bfloat162float(h));
        int idx = (img * 144 + p) * 40 + ic;
        xh[idx] = h;
        xl[idx] = l;
    }

    int wm = wid & 3, wn = wid >> 2;
    int rowoff8 = ((lid >> 3) & 1) * 8 + (lid & 7);
    int colb = (lid >= 16) ? 16 : 0;
    uint32_t baseA[2];
#pragma unroll
    for (int mh = 0; mh < 2; mh++) {
        int m = wm * 32 + mh * 16 + rowoff8;
        int img = m >> 6, p = m & 63;
        int prow = img * 144 + (p >> 3) * 12 + (p & 7);
        baseA[mh] = (uint32_t)(prow * 80 + colb);
    }
    uint32_t baseB[2];
#pragma unroll
    for (int nh = 0; nh < 2; nh++)
        baseB[nh] = (uint32_t)(OFF_B + rowoff8 * 144 + wn * 64 + colb + nh * 32);
    uint32_t sbXH = sb + OFF_XH, sbXL = sb + OFF_XL;

    float acc[2][4][4] = {};

    int sG = 0;
    const int cellS[3] = {0, 13, 25};
#pragma unroll 1
    for (int hch = 0; hch < 2; hch++) {
        int k0 = cellS[hch] * 32;
        int rows = (cellS[hch + 1] - cellS[hch]) * 32;
        __syncthreads();
        for (int i = tid; i < rows * 8; i += 256) {
            int row = i >> 3, c = i & 7;
            *(uint4*)(smem + OFF_B + row * 144 + c * 16) =
                *(const uint4*)(g_w2bf + (size_t)(k0 + row) * 64 + c * 8);
        }
        __syncthreads();
        int nsteps = (rows >> 4);
#pragma unroll 1
        for (int ss = 0; ss < nsteps; ss++, sG++) {
            int koff = s_koff[sG];
            uint32_t aH0[4], aH1[4], aL0[4], aL1[4], bu[4], bv[4];
            ldsm_x4(aH0[0], aH0[1], aH0[2], aH0[3], sbXH + baseA[0] + koff);
            ldsm_x4(aH1[0], aH1[1], aH1[2], aH1[3], sbXH + baseA[1] + koff);
            ldsm_x4(aL0[0], aL0[1], aL0[2], aL0[3], sbXL + baseA[0] + koff);
            ldsm_x4(aL1[0], aL1[1], aL1[2], aL1[3], sbXL + baseA[1] + koff);
            uint32_t bro = (uint32_t)(ss * 2304);
            ldsm_x4t(bu[0], bu[1], bu[2], bu[3], sb + baseB[0] + bro);
            ldsm_x4t(bv[0], bv[1], bv[2], bv[3], sb + baseB[1] + bro);

            mma16816(acc[0][0], aH0, bu[0], bu[1]);
            mma16816(acc[0][1], aH0, bu[2], bu[3]);
            mma16816(acc[0][2], aH0, bv[0], bv[1]);
            mma16816(acc[0][3], aH0, bv[2], bv[3]);
            mma16816(acc[1][0], aH1, bu[0], bu[1]);
            mma16816(acc[1][1], aH1, bu[2], bu[3]);
            mma16816(acc[1][2], aH1, bv[0], bv[1]);
            mma16816(acc[1][3], aH1, bv[2], bv[3]);
            mma16816(acc[0][0], aL0, bu[0], bu[1]);
            mma16816(acc[0][1], aL0, bu[2], bu[3]);
            mma16816(acc[0][2], aL0, bv[0], bv[1]);
            mma16816(acc[0][3], aL0, bv[2], bv[3]);
            mma16816(acc[1][0], aL1, bu[0], bu[1]);
            mma16816(acc[1][1], aL1, bu[2], bu[3]);
            mma16816(acc[1][2], aL1, bv[0], bv[1]);
            mma16816(acc[1][3], aL1, bv[2], bv[3]);
        }
    }
    __syncthreads();

    float* s_tr = (float*)smem;
#pragma unroll
    for (int mh = 0; mh < 2; mh++) {
#pragma unroll
        for (int j = 0; j < 4; j++) {
#pragma unroll
            for (int rg = 0; rg < 4; rg++) {
                int row = wm * 32 + mh * 16 + (lid >> 2) + ((rg >= 2) ? 8 : 0);
                int col = wn * 32 + j * 8 + (lid & 3) * 2 + (rg & 1);
                s_tr[row * 65 + col] = acc[mh][j][rg] * s_alpha[col] + s_bias[col];
            }
        }
    }
    __syncthreads();

    if (tid < 128) {
        int col = tid & 63, half = tid >> 6;
        float su = 0.f, sq = 0.f;
#pragma unroll 4
        for (int j = 0; j < 64; j++) {
            float v = s_tr[(half * 64 + j) * 65 + col];
            su += v; sq += v * v;
        }
        s_psum[half * 64 + col] = su;
        s_psq[half * 64 + col] = sq;
    }
    for (int i = 0; i < 8; i++) {
        int fl = i * 256 + tid;
        int oc = fl & 63, px = (fl >> 6) & 3, py = (fl >> 8) & 3, img = fl >> 10;
        int r0 = img * 64 + py * 16 + px * 2;
        float a = s_tr[r0 * 65 + oc];
        float b = s_tr[(r0 + 1) * 65 + oc];
        float cv = s_tr[(r0 + 8) * 65 + oc];
        float dv = s_tr[(r0 + 9) * 65 + oc];
        g_pool2pre[(size_t)(n0 + img) * 1024 + oc * 16 + py * 4 + px] =
            fmaxf(fmaxf(a, b), fmaxf(cv, dv));
    }
    __syncthreads();
    if (tid < 64) {
        g_ps2[blockIdx.x * 64 + tid] = s_psum[tid] + s_psum[64 + tid];
        g_pq2[blockIdx.x * 64 + tid] = s_psq[tid] + s_psq[64 + tid];
    }
}

// ================= fc1 via mma.sync: 128x64 tiles, K=1024 =================
__global__ void __launch_bounds__(256) k_fc1_mma(const float* __restrict__ bias) {
    __shared__ __align__(16) __nv_bfloat16 Ah[128 * 40];
    __shared__ __align__(16) __nv_bfloat16 Al[128 * 40];
    __shared__ __align__(16) __nv_bfloat16 Bs[32 * 72];
    __shared__ float s_sc[64], s_sh[64], s_al[64], s_bi[64];

    int tid = threadIdx.x, wid = tid >> 5, lid = tid & 31;
    int brow = blockIdx.y * 128, bcol = blockIdx.x * 64;
    if (tid < 64) {
        s_sc[tid] = g_bns2[tid]; s_sh[tid] = g_bnb2[tid];
        s_al[tid] = g_alphaf1[bcol + tid]; s_bi[tid] = bias[bcol + tid];
    }

    int wm = wid & 3, wn = wid >> 2;
    int rowoff8 = ((lid >> 3) & 1) * 8 + (lid & 7);
    int colb = (lid >= 16) ? 16 : 0;
    uint32_t sbAh = smem_u32(Ah), sbAl = smem_u32(Al), sbB = smem_u32(Bs);

    float acc[2][4][4] = {};

#pragma unroll 1
    for (int kc = 0; kc < 1024; kc += 32) {
        __syncthreads();
        for (int i = tid; i < 1024; i += 256) {
            int r = i >> 3, c4 = i & 7;
            int ch = (kc + c4 * 4) >> 4;
            float4 v = *(const float4*)&g_pool2pre[(size_t)(brow + r) * 1024 + kc + c4 * 4];
            float sc = s_sc[ch], sh = s_sh[ch];
            float f0 = fmaxf(v.x * sc + sh, 0.f);
            float f1 = fmaxf(v.y * sc + sh, 0.f);
            float f2 = fmaxf(v.z * sc + sh, 0.f);
            float f3 = fmaxf(v.w * sc + sh, 0.f);
            __nv_bfloat16 h0 = __float2bfloat16(f0), h1 = __float2bfloat16(f1);
            __nv_bfloat16 h2 = __float2bfloat16(f2), h3 = __float2bfloat16(f3);
            __nv_bfloat162* ph = (__nv_bfloat162*)&Ah[r * 40 + c4 * 4];
            __nv_bfloat162* pl = (__nv_bfloat162*)&Al[r * 40 + c4 * 4];
            ph[0] = __nv_bfloat162(h0, h1);
            ph[1] = __nv_bfloat162(h2, h3);
            pl[0] = __nv_bfloat162(__float2bfloat16(f0 - __bfloat162float(h0)),
                                   __float2bfloat16(f1 - __bfloat162float(h1)));
            pl[1] = __nv_bfloat162(__float2bfloat16(f2 - __bfloat162float(h2)),
                                   __float2bfloat16(f3 - __bfloat162float(h3)));
        }
        if (tid < 256) {
            int r = tid >> 3, c8 = tid & 7;
            *(uint4*)&Bs[r * 72 + c8 * 8] =
                *(const uint4*)&g_wf1bf[(size_t)(kc + r) * 512 + bcol + c8 * 8];
        }
        __syncthreads();
#pragma unroll
        for (int ks = 0; ks < 2; ks++) {
            uint32_t aH[2][4], aL[2][4], bu[2][4];
#pragma unroll
            for (int mh = 0; mh < 2; mh++) {
                uint32_t ra = (uint32_t)((wm * 32 + mh * 16 + rowoff8) * 80 + colb + ks * 32);
                ldsm_x4(aH[mh][0], aH[mh][1], aH[mh][2], aH[mh][3], sbAh + ra);
                ldsm_x4(aL[mh][0], aL[mh][1], aL[mh][2], aL[mh][3], sbAl + ra);
            }
#pragma unroll
            for (int nb = 0; nb < 2; nb++) {
                uint32_t rb = (uint32_t)((ks * 16 + rowoff8) * 144 + wn * 64 + nb * 32 + colb);
                ldsm_x4t(bu[nb][0], bu[nb][1], bu[nb][2], bu[nb][3], sbB + rb);
            }
#pragma unroll
            for (int mh = 0; mh < 2; mh++) {
                mma16816(acc[mh][0], aH[mh], bu[0][0], bu[0][1]);
                mma16816(acc[mh][1], aH[mh], bu[0][2], bu[0][3]);
                mma16816(acc[mh][2], aH[mh], bu[1][0], bu[1][1]);
                mma16816(acc[mh][3], aH[mh], bu[1][2], bu[1][3]);
                mma16816(acc[mh][0], aL[mh], bu[0][0], bu[0][1]);
                mma16816(acc[mh][1], aL[mh], bu[0][2], bu[0][3]);
                mma16816(acc[mh][2], aL[mh], bu[1][0], bu[1][1]);
                mma16816(acc[mh][3], aL[mh], bu[1][2], bu[1][3]);
            }
        }
    }
#pragma unroll
    for (int mh = 0; mh < 2; mh++) {
#pragma unroll
        for (int nb = 0; nb < 4; nb++) {
#pragma unroll
            for (int rp = 0; rp < 2; rp++) {
                int row = brow + wm * 32 + mh * 16 + (lid >> 2) + rp * 8;
                int cl = wn * 32 + nb * 8 + (lid & 3) * 2;
                float v0 = fmaxf(acc[mh][nb][rp * 2] * s_al[cl] + s_bi[cl], 0.f);
                float v1 = fmaxf(acc[mh][nb][rp * 2 + 1] * s_al[cl + 1] + s_bi[cl + 1], 0.f);
                *(float2*)&g_fc1o[(size_t)row * 512 + bcol + cl] = make_float2(v0, v1);
            }
        }
    }
}

// ================= fc2 =================
__global__ void __launch_bounds__(256) k_fc2(const float* __restrict__ bias,
                                             float* __restrict__ out) {
    __shared__ float s_w[5120];
    __shared__ float s_b[10];
    int tid = threadIdx.x;
    for (int i = tid; i < 5120; i += 256) s_w[i] = g_twf2[i];
    if (tid < 10) s_b[tid] = bias[tid];
    __syncthreads();
    int wid = tid >> 5, lane = tid & 31;
    int img = blockIdx.x * 8 + wid;
    const float* xr = g_fc1o + (size_t)img * 512;
    float acc[10];
#pragma unroll
    for (int j = 0; j < 10; j++) acc[j] = 0.f;
    for (int k = lane; k < 512; k += 32) {
        float xv = xr[k];
#pragma unroll
        for (int j = 0; j < 10; j++) acc[j] += xv * s_w[j * 512 + k];
    }
#pragma unroll
    for (int j = 0; j < 10; j++)
        for (int o = 16; o; o >>= 1) acc[j] += __shfl_xor_sync(0xffffffffu, acc[j], o);
    if (lane == 0) {
#pragma unroll
        for (int j = 0; j < 10; j++) out[(size_t)img * 10 + j] = acc[j] + s_b[j];
    }
}

// ================= launch =================
extern "C" void kernel_launch(void* const* d_in, const int* in_sizes, int n_in,
                              void* d_out, int out_size) {
    const float* x   = (const float*)d_in[0];
    const float* w1  = (const float*)d_in[1];
    const float* b1  = (const float*)d_in[2];
    const float* ga1 = (const float*)d_in[3];
    const float* be1 = (const float*)d_in[4];
    const float* w2  = (const float*)d_in[5];
    const float* b2  = (const float*)d_in[6];
    const float* ga2 = (const float*)d_in[7];
    const float* be2 = (const float*)d_in[8];
    const float* wf1 = (const float*)d_in[9];
    const float* bf1 = (const float*)d_in[10];
    const float* wf2 = (const float*)d_in[11];
    const float* bf2 = (const float*)d_in[12];
    float* out = (float*)d_out;

    cudaFuncSetAttribute(k_conv1_mma, cudaFuncAttributeMaxDynamicSharedMemorySize, SMEM1);
    cudaFuncSetAttribute(k_conv2_mma, cudaFuncAttributeMaxDynamicSharedMemorySize, SMEM_MMA);

    k_ternarize_all<<<618, 256>>>(w1, w2, wf1, wf2);
    k_prepw2<<<200, 256>>>();
    k_prepwf1<<<2048, 256>>>();
    k_conv1_mma<<<NB, 288, SMEM1>>>(x, b1);
    k_bnstats<<<32, 256>>>(1, ga1, be1);
    k_conv2_mma<<<NB / 2, 256, SMEM_MMA>>>(b2);
    k_bnstats<<<64, 256>>>(2, ga2, be2);
    k_fc1_mma<<<dim3(512 / 64, NB / 128), 256>>>(bf1);
    k_fc2<<<NB / 8, 256>>>(bf2, out);
}

// round 17
// speedup vs baseline: 1.5849x; 1.5849x over previous
#include <cuda_runtime.h>
#include <cuda_bf16.h>
#include <cuda_fp16.h>
#include <math.h>
#include <stdint.h>

#define NB 4096
typedef unsigned long long u64;

// ================= mma.sync / ldmatrix helpers =================
__device__ __forceinline__ uint32_t smem_u32(const void* p) {
    uint32_t a;
    asm("{ .reg .u64 t; cvta.to.shared.u64 t, %1; cvt.u32.u64 %0, t; }" : "=r"(a) : "l"(p));
    return a;
}
__device__ __forceinline__ void ldsm_x4(uint32_t &r0, uint32_t &r1, uint32_t &r2, uint32_t &r3,
                                        uint32_t addr) {
    asm volatile("ldmatrix.sync.aligned.m8n8.x4.shared.b16 {%0,%1,%2,%3}, [%4];"
                 : "=r"(r0), "=r"(r1), "=r"(r2), "=r"(r3) : "r"(addr));
}
__device__ __forceinline__ void ldsm_x4t(uint32_t &r0, uint32_t &r1, uint32_t &r2, uint32_t &r3,
                                         uint32_t addr) {
    asm volatile("ldmatrix.sync.aligned.m8n8.x4.trans.shared.b16 {%0,%1,%2,%3}, [%4];"
                 : "=r"(r0), "=r"(r1), "=r"(r2), "=r"(r3) : "r"(addr));
}
__device__ __forceinline__ void mma16816(float* d, const uint32_t* a, uint32_t b0, uint32_t b1) {
    asm volatile(
        "mma.sync.aligned.m16n8k16.row.col.f32.bf16.bf16.f32 "
        "{%0,%1,%2,%3}, {%4,%5,%6,%7}, {%8,%9}, {%0,%1,%2,%3};"
        : "+f"(d[0]), "+f"(d[1]), "+f"(d[2]), "+f"(d[3])
        : "r"(a[0]), "r"(a[1]), "r"(a[2]), "r"(a[3]), "r"(b0), "r"(b1));
}
__device__ __forceinline__ void mma16816h(float* d, const uint32_t* a, uint32_t b0, uint32_t b1) {
    asm volatile(
        "mma.sync.aligned.m16n8k16.row.col.f32.f16.f16.f32 "
        "{%0,%1,%2,%3}, {%4,%5,%6,%7}, {%8,%9}, {%0,%1,%2,%3};"
        : "+f"(d[0]), "+f"(d[1]), "+f"(d[2]), "+f"(d[3])
        : "r"(a[0]), "r"(a[1]), "r"(a[2]), "r"(a[3]), "r"(b0), "r"(b1));
}
__device__ __forceinline__ uint32_t pkhf(float a, float b) {
    __half2 t(__float2half(a), __float2half(b));
    uint32_t r; asm("mov.b32 %0, %1;" : "=r"(r) : "r"(*(uint32_t*)&t)); return r;
}

// ================= scratch =================
__device__ float g_tw1t[25 * 32];        // conv1 SIGNS [tap][oc]
__device__ float g_alpha1[32];
__device__ float g_tw2t[800 * 64];       // conv2 SIGNS [ic*25+t][oc]
__device__ float g_alpha2[64];
__device__ float g_twf1[512 * 1024];     // fc1 SIGNS [oc][k]
__device__ float g_alphaf1[512];
__device__ float g_twf2[10 * 512];       // fc2 full tern values
__device__ __align__(16) __nv_bfloat16 g_w2bf[800 * 64];    // conv2 T bf16, k=(t*32+ic)
__device__ __align__(16) __nv_bfloat16 g_wf1bf[1024 * 512]; // fc1 T bf16 [k][oc]

__device__ float g_pool1pre[(size_t)NB * 32 * 144];  // pooled pre-BN conv1 [n][pos*32+ic]
__device__ float g_pool2pre[(size_t)NB * 1024];      // pooled pre-BN conv2 [n][oc*16+pos]
__device__ float g_fc1o[(size_t)NB * 512];

__device__ float g_ps1[NB * 32], g_pq1[NB * 32];
__device__ float g_ps2[(NB / 2) * 64], g_pq2[(NB / 2) * 64];
__device__ float g_bns1[32], g_bnb1[32];
__device__ float g_bns2[64], g_bnb2[64];

// ================= ternarize =================
__global__ void __launch_bounds__(256) k_ternarize_all(const float* __restrict__ w1,
                                                       const float* __restrict__ w2,
                                                       const float* __restrict__ wf1,
                                                       const float* __restrict__ wf2) {
    int b = blockIdx.x;
    const float* wc; int per, mode, ch;
    if (b < 32)       { ch = b;       wc = w1  + (size_t)ch * 25;   per = 25;   mode = 0; }
    else if (b < 96)  { ch = b - 32;  wc = w2  + (size_t)ch * 800;  per = 800;  mode = 1; }
    else if (b < 608) { ch = b - 96;  wc = wf1 + (size_t)ch * 1024; per = 1024; mode = 2; }
    else              { ch = b - 608; wc = wf2 + (size_t)ch * 512;  per = 512;  mode = 3; }

    int tid = threadIdx.x;
    __shared__ float sA[8], sB[8];
    __shared__ float s_delta, s_alpha;

    float s = 0.f;
    for (int i = tid; i < per; i += 256) s += fabsf(wc[i]);
    for (int o = 16; o; o >>= 1) s += __shfl_xor_sync(0xffffffffu, s, o);
    if ((tid & 31) == 0) sA[tid >> 5] = s;
    __syncthreads();
    if (tid == 0) {
        float t = 0.f;
        for (int i = 0; i < 8; i++) t += sA[i];
        s_delta = 0.7f * t / (float)per;
    }
    __syncthreads();
    float delta = s_delta;

    float sa = 0.f, cn = 0.f;
    for (int i = tid; i < per; i += 256) {
        float a = fabsf(wc[i]);
        if (a > delta) { sa += a; cn += 1.f; }
    }
    for (int o = 16; o; o >>= 1) {
        sa += __shfl_xor_sync(0xffffffffu, sa, o);
        cn += __shfl_xor_sync(0xffffffffu, cn, o);
    }
    __syncthreads();
    if ((tid & 31) == 0) { sA[tid >> 5] = sa; sB[tid >> 5] = cn; }
    __syncthreads();
    if (tid == 0) {
        float a = 0.f, c = 0.f;
        for (int i = 0; i < 8; i++) { a += sA[i]; c += sB[i]; }
        s_alpha = a / c;
    }
    __syncthreads();
    float alpha = s_alpha;
    if (tid == 0) {
        if (mode == 0) g_alpha1[ch] = alpha;
        if (mode == 1) g_alpha2[ch] = alpha;
        if (mode == 2) g_alphaf1[ch] = alpha;
    }
    for (int i = tid; i < per; i += 256) {
        float v = wc[i];
        bool on = fabsf(v) > delta;
        float sgn = on ? copysignf(1.f, v) : 0.f;
        if (mode == 0)      g_tw1t[i * 32 + ch] = sgn;
        else if (mode == 1) g_tw2t[i * 64 + ch] = sgn;
        else if (mode == 2) g_twf1[(size_t)ch * 1024 + i] = sgn;
        else                g_twf2[ch * 512 + i] = on ? copysignf(alpha, v) : 0.f;
    }
}

// ---- conv2 weight prep ----
__global__ void __launch_bounds__(256) k_prepw2() {
    int f = blockIdx.x * 256 + threadIdx.x;
    if (f >= 51200) return;
    int k = f >> 6, oc = f & 63;
    int t = k >> 5, ic = k & 31;
    g_w2bf[k * 64 + oc] = __float2bfloat16(g_tw2t[(ic * 25 + t) * 64 + oc]);
}

// ---- fc1 weight prep ----
__global__ void __launch_bounds__(256) k_prepwf1() {
    int f = blockIdx.x * 256 + threadIdx.x;
    if (f >= 524288) return;
    int k = f >> 9, oc = f & 511;
    g_wf1bf[(size_t)k * 512 + oc] = __float2bfloat16(g_twf1[(size_t)oc * 1024 + k]);
}

// ================= conv1 via mma.sync (fp16 single-chain, staged im2col) ==========
// 1 image/CTA, 288 threads (9 warps x 4 m16 tiles). M=576 pooled-quad-major,
// N=32 oc, K=32 (25 taps + 7 zero). A fp16 plane (exact-weight f16 MMA), 80B rows.
#define OFF1_X 0
#define OFF1_A 3200
#define OFF1_B  (OFF1_A + 576 * 80)      // 49280
#define OFF1_MISC (OFF1_B + 32 * 80)     // 51840
#define SMEM1 (OFF1_MISC + 2816)         // 54656 -> 4 CTAs/SM

extern "C" __global__ void __launch_bounds__(288) k_conv1_mma(const float* __restrict__ x,
                                                              const float* __restrict__ bias) {
    extern __shared__ __align__(16) uint8_t smem[];
    uint32_t sb = smem_u32(smem);
    int n = blockIdx.x, tid = threadIdx.x, wid = tid >> 5, lid = tid & 31;

    float* s_x = (float*)(smem + OFF1_X);
    float* s_alpha = (float*)(smem + OFF1_MISC);
    float* s_bias  = (float*)(smem + OFF1_MISC + 128);
    float* s_ps    = (float*)(smem + OFF1_MISC + 256);    // [9][32]
    float* s_pq    = (float*)(smem + OFF1_MISC + 1408);   // [9][32]

    if (tid < 32) { s_alpha[tid] = g_alpha1[tid]; s_bias[tid] = bias[tid]; }
    for (int i = tid; i < 196; i += 288)
        ((float4*)s_x)[i] = ((const float4*)(x + (size_t)n * 784))[i];
    // B: [32 k][40 fp16] rows, taps 0..24 real, rest zero (signs exact in fp16)
    for (int i = tid; i < 640; i += 288) {
        int row = i / 20, c = i - (i / 20) * 20;
        float a = 0.f, b2 = 0.f;
        if (row < 25 && c < 16) {
            a = g_tw1t[row * 32 + c * 2];
            b2 = g_tw1t[row * 32 + c * 2 + 1];
        }
        ((uint32_t*)(smem + OFF1_B + row * 80))[c] = pkhf(a, b2);
    }
    __syncthreads();

    // build im2col A (fp16), pooled-quad-major rows; vectorized STS.128
    for (int m = tid; m < 576; m += 288) {
        int pp = m >> 2, q = m & 3;
        int oy = 2 * (pp / 12) + (q >> 1);
        int ox = 2 * (pp - (pp / 12) * 12) + (q & 1);
        float v[25];
#pragma unroll
        for (int ky = 0; ky < 5; ky++) {
            const float* xr = &s_x[(oy + ky) * 28 + ox];
#pragma unroll
            for (int kx = 0; kx < 5; kx++) v[ky * 5 + kx] = xr[kx];
        }
        uint32_t wh[16];
#pragma unroll
        for (int t = 0; t < 12; t++) wh[t] = pkhf(v[2 * t], v[2 * t + 1]);
        wh[12] = pkhf(v[24], 0.f);
#pragma unroll
        for (int t = 13; t < 16; t++) wh[t] = 0u;
        uint4* rh = (uint4*)(smem + OFF1_A + m * 80);
#pragma unroll
        for (int t = 0; t < 4; t++)
            rh[t] = make_uint4(wh[4 * t], wh[4 * t + 1], wh[4 * t + 2], wh[4 * t + 3]);
    }
    __syncthreads();

    int rowoff8 = ((lid >> 3) & 1) * 8 + (lid & 7);
    int colb = (lid >= 16) ? 16 : 0;
    uint32_t sbA = sb + OFF1_A, sbB = sb + OFF1_B;

    uint32_t Bf[2][2][4];
#pragma unroll
    for (int ks = 0; ks < 2; ks++)
#pragma unroll
        for (int nb = 0; nb < 2; nb++)
            ldsm_x4t(Bf[ks][nb][0], Bf[ks][nb][1], Bf[ks][nb][2], Bf[ks][nb][3],
                     sbB + (uint32_t)((ks * 16 + rowoff8) * 80 + nb * 32 + colb));

    float biasv[8], alphav[8];
#pragma unroll
    for (int j = 0; j < 4; j++) {
        int c = j * 8 + (lid & 3) * 2;
        biasv[j * 2] = s_bias[c];         alphav[j * 2] = s_alpha[c];
        biasv[j * 2 + 1] = s_bias[c + 1]; alphav[j * 2 + 1] = s_alpha[c + 1];
    }
    float su[8] = {}, sq[8] = {};

#pragma unroll 1
    for (int t = wid * 4; t < wid * 4 + 4; t++) {
        float acc[4][4] = {};
#pragma unroll
        for (int ks = 0; ks < 2; ks++) {
            uint32_t ra = (uint32_t)((t * 16 + rowoff8) * 80 + colb + ks * 32);
            uint32_t aH[4];
            ldsm_x4(aH[0], aH[1], aH[2], aH[3], sbA + ra);
#pragma unroll
            for (int nb = 0; nb < 2; nb++) {
                mma16816h(acc[nb * 2 + 0], aH, Bf[ks][nb][0], Bf[ks][nb][1]);
                mma16816h(acc[nb * 2 + 1], aH, Bf[ks][nb][2], Bf[ks][nb][3]);
            }
        }
#pragma unroll
        for (int j = 0; j < 4; j++) {
            float v0 = acc[j][0] * alphav[j * 2] + biasv[j * 2];
            float v1 = acc[j][1] * alphav[j * 2 + 1] + biasv[j * 2 + 1];
            float v2 = acc[j][2] * alphav[j * 2] + biasv[j * 2];
            float v3 = acc[j][3] * alphav[j * 2 + 1] + biasv[j * 2 + 1];
            su[j * 2]     += v0 + v2;
            su[j * 2 + 1] += v1 + v3;
            sq[j * 2]     += v0 * v0 + v2 * v2;
            sq[j * 2 + 1] += v1 * v1 + v3 * v3;
            float m0 = v0, m1 = v1, m2 = v2, m3 = v3;
            m0 = fmaxf(m0, __shfl_xor_sync(0xffffffffu, m0, 4));
            m1 = fmaxf(m1, __shfl_xor_sync(0xffffffffu, m1, 4));
            m2 = fmaxf(m2, __shfl_xor_sync(0xffffffffu, m2, 4));
            m3 = fmaxf(m3, __shfl_xor_sync(0xffffffffu, m3, 4));
            m0 = fmaxf(m0, __shfl_xor_sync(0xffffffffu, m0, 8));
            m1 = fmaxf(m1, __shfl_xor_sync(0xffffffffu, m1, 8));
            m2 = fmaxf(m2, __shfl_xor_sync(0xffffffffu, m2, 8));
            m3 = fmaxf(m3, __shfl_xor_sync(0xffffffffu, m3, 8));
            if ((lid & 12) == 0) {
                int g = (lid >> 4);
                int pp0 = t * 4 + g;
                int pp2 = t * 4 + 2 + g;
                int col = j * 8 + (lid & 3) * 2;
                float* base = &g_pool1pre[(size_t)n * 4608];
                *(float2*)&base[pp0 * 32 + col] = make_float2(m0, m1);
                *(float2*)&base[pp2 * 32 + col] = make_float2(m2, m3);
            }
        }
    }
#pragma unroll
    for (int c = 0; c < 8; c++) {
        for (int o = 4; o <= 16; o <<= 1) {
            su[c] += __shfl_xor_sync(0xffffffffu, su[c], o);
            sq[c] += __shfl_xor_sync(0xffffffffu, sq[c], o);
        }
    }
    if (lid < 4) {
#pragma unroll
        for (int j = 0; j < 4; j++) {
            int c = j * 8 + lid * 2;
            s_ps[wid * 32 + c] = su[j * 2];         s_pq[wid * 32 + c] = sq[j * 2];
            s_ps[wid * 32 + c + 1] = su[j * 2 + 1]; s_pq[wid * 32 + c + 1] = sq[j * 2 + 1];
        }
    }
    __syncthreads();
    if (tid < 32) {
        float a = 0.f, q2 = 0.f;
#pragma unroll
        for (int w = 0; w < 9; w++) { a += s_ps[w * 32 + tid]; q2 += s_pq[w * 32 + tid]; }
        g_ps1[n * 32 + tid] = a;
        g_pq1[n * 32 + tid] = q2;
    }
}

// ================= BN stats =================
__global__ void __launch_bounds__(256) k_bnstats(int which,
                                                 const float* __restrict__ gamma,
                                                 const float* __restrict__ beta) {
    const int C = (which == 1) ? 32 : 64;
    const int cnt = (which == 1) ? NB : (NB / 2);
    const float* ps = (which == 1) ? g_ps1 : g_ps2;
    const float* pq = (which == 1) ? g_pq1 : g_pq2;
    float* scale = (which == 1) ? g_bns1 : g_bns2;
    float* shift = (which == 1) ? g_bnb1 : g_bnb2;
    const float inv_count = (which == 1) ? (1.f / (4096.f * 576.f)) : (1.f / (4096.f * 64.f));

    int c = blockIdx.x, tid = threadIdx.x;
    __shared__ float sA[8], sB[8];
    float s = 0.f, q = 0.f;
    for (int i = tid; i < cnt; i += 256) { s += ps[i * C + c]; q += pq[i * C + c]; }
    for (int o = 16; o; o >>= 1) {
        s += __shfl_xor_sync(0xffffffffu, s, o);
        q += __shfl_xor_sync(0xffffffffu, q, o);
    }
    if ((tid & 31) == 0) { sA[tid >> 5] = s; sB[tid >> 5] = q; }
    __syncthreads();
    if (tid == 0) {
        float ts = 0.f, tq = 0.f;
        for (int i = 0; i < 8; i++) { ts += sA[i]; tq += sB[i]; }
        float mean = ts * inv_count;
        float var = tq * inv_count - mean * mean;
        float sc = gamma[c] * rsqrtf(var + 1e-5f);
        scale[c] = sc;
        shift[c] = beta[c] - mean * sc;
    }
}

// ================= conv2 via mma.sync (5 B-chunks of 160 rows -> 3 CTAs/SM) ========
#define OFF_B 0
#define B_ROWS 160
#define OFF_XH (B_ROWS * 144)               // 23040
#define OFF_XL (OFF_XH + 288 * 80)          // 46080
#define OFF_MISC (OFF_XL + 288 * 80)        // 69120
#define SMEM_MMA (OFF_MISC + 2048)          // 71168

extern "C" __global__ void __launch_bounds__(256) k_conv2_mma(const float* __restrict__ bias) {
    extern __shared__ __align__(16) uint8_t smem[];
    uint32_t sb = smem_u32(smem);
    int tid = threadIdx.x, wid = tid >> 5, lid = tid & 31;
    int n0 = blockIdx.x * 2;

    float* s_bias  = (float*)(smem + OFF_MISC);
    float* s_alpha = (float*)(smem + OFF_MISC + 256);
    float* s_s1    = (float*)(smem + OFF_MISC + 512);
    float* s_h1    = (float*)(smem + OFF_MISC + 640);
    int*   s_koff  = (int*)(smem + OFF_MISC + 768);
    float* s_psum  = (float*)(smem + OFF_MISC + 1024);
    float* s_psq   = (float*)(smem + OFF_MISC + 1536);

    if (tid < 64) { s_bias[tid] = bias[tid]; s_alpha[tid] = g_alpha2[tid]; }
    if (tid < 32) { s_s1[tid] = g_bns1[tid]; s_h1[tid] = g_bnb1[tid]; }
    if (tid < 50) {
        int t = tid >> 1;
        s_koff[tid] = ((t / 5) * 12 + (t % 5)) * 80 + (tid & 1) * 32;
    }
    __syncthreads();

    __nv_bfloat16* xh = (__nv_bfloat16*)(smem + OFF_XH);
    __nv_bfloat16* xl = (__nv_bfloat16*)(smem + OFF_XL);
    for (int e = tid; e < 9216; e += 256) {
        int img = e / 4608, rem = e - img * 4608;
        int p = rem >> 5, ic = rem & 31;     // [pos][ic] layout from conv1_mma
        float v = g_pool1pre[(size_t)(n0 + img) * 4608 + rem];
        v = fmaxf(v * s_s1[ic] + s_h1[ic], 0.f);
        __nv_bfloat16 h = __float2bfloat16(v);
        __nv_bfloat16 l = __float2bfloat16(v - __bfloat162float(h));
        int idx = (img * 144 + p) * 40 + ic;
        xh[idx] = h;
        xl[idx] = l;
    }

    int wm = wid & 3, wn = wid >> 2;
    int rowoff8 = ((lid >> 3) & 1) * 8 + (lid & 7);
    int colb = (lid >= 16) ? 16 : 0;
    uint32_t baseA[2];
#pragma unroll
    for (int mh = 0; mh < 2; mh++) {
        int m = wm * 32 + mh * 16 + rowoff8;
        int img = m >> 6, p = m & 63;
        int prow = img * 144 + (p >> 3) * 12 + (p & 7);
        baseA[mh] = (uint32_t)(prow * 80 + colb);
    }
    uint32_t baseB[2];
#pragma unroll
    for (int nh = 0; nh < 2; nh++)
        baseB[nh] = (uint32_t)(OFF_B + rowoff8 * 144 + wn * 64 + colb + nh * 32);
    uint32_t sbXH = sb + OFF_XH, sbXL = sb + OFF_XL;

    float acc[2][4][4] = {};

    int sG = 0;
#pragma unroll 1
    for (int hch = 0; hch < 5; hch++) {
        int k0 = hch * B_ROWS;
        __syncthreads();
        for (int i = tid; i < B_ROWS * 8; i += 256) {
            int row = i >> 3, c = i & 7;
            *(uint4*)(smem + OFF_B + row * 144 + c * 16) =
                *(const uint4*)(g_w2bf + (size_t)(k0 + row) * 64 + c * 8);
        }
        __syncthreads();
#pragma unroll 1
        for (int ss = 0; ss < 10; ss++, sG++) {
            int koff = s_koff[sG];
            uint32_t aH0[4], aH1[4], aL0[4], aL1[4], bu[4], bv[4];
            ldsm_x4(aH0[0], aH0[1], aH0[2], aH0[3], sbXH + baseA[0] + koff);
            ldsm_x4(aH1[0], aH1[1], aH1[2], aH1[3], sbXH + baseA[1] + koff);
            ldsm_x4(aL0[0], aL0[1], aL0[2], aL0[3], sbXL + baseA[0] + koff);
            ldsm_x4(aL1[0], aL1[1], aL1[2], aL1[3], sbXL + baseA[1] + koff);
            uint32_t bro = (uint32_t)(ss * 2304);
            ldsm_x4t(bu[0], bu[1], bu[2], bu[3], sb + baseB[0] + bro);
            ldsm_x4t(bv[0], bv[1], bv[2], bv[3], sb + baseB[1] + bro);

            mma16816(acc[0][0], aH0, bu[0], bu[1]);
            mma16816(acc[0][1], aH0, bu[2], bu[3]);
            mma16816(acc[0][2], aH0, bv[0], bv[1]);
            mma16816(acc[0][3], aH0, bv[2], bv[3]);
            mma16816(acc[1][0], aH1, bu[0], bu[1]);
            mma16816(acc[1][1], aH1, bu[2], bu[3]);
            mma16816(acc[1][2], aH1, bv[0], bv[1]);
            mma16816(acc[1][3], aH1, bv[2], bv[3]);
            mma16816(acc[0][0], aL0, bu[0], bu[1]);
            mma16816(acc[0][1], aL0, bu[2], bu[3]);
            mma16816(acc[0][2], aL0, bv[0], bv[1]);
            mma16816(acc[0][3], aL0, bv[2], bv[3]);
            mma16816(acc[1][0], aL1, bu[0], bu[1]);
            mma16816(acc[1][1], aL1, bu[2], bu[3]);
            mma16816(acc[1][2], aL1, bv[0], bv[1]);
            mma16816(acc[1][3], aL1, bv[2], bv[3]);
        }
    }
    __syncthreads();

    float* s_tr = (float*)smem;
#pragma unroll
    for (int mh = 0; mh < 2; mh++) {
#pragma unroll
        for (int j = 0; j < 4; j++) {
#pragma unroll
            for (int rg = 0; rg < 4; rg++) {
                int row = wm * 32 + mh * 16 + (lid >> 2) + ((rg >= 2) ? 8 : 0);
                int col = wn * 32 + j * 8 + (lid & 3) * 2 + (rg & 1);
                s_tr[row * 65 + col] = acc[mh][j][rg] * s_alpha[col] + s_bias[col];
            }
        }
    }
    __syncthreads();

    if (tid < 128) {
        int col = tid & 63, half = tid >> 6;
        float su = 0.f, sq = 0.f;
#pragma unroll 4
        for (int j = 0; j < 64; j++) {
            float v = s_tr[(half * 64 + j) * 65 + col];
            su += v; sq += v * v;
        }
        s_psum[half * 64 + col] = su;
        s_psq[half * 64 + col] = sq;
    }
    for (int i = 0; i < 8; i++) {
        int fl = i * 256 + tid;
        int oc = fl & 63, px = (fl >> 6) & 3, py = (fl >> 8) & 3, img = fl >> 10;
        int r0 = img * 64 + py * 16 + px * 2;
        float a = s_tr[r0 * 65 + oc];
        float b = s_tr[(r0 + 1) * 65 + oc];
        float cv = s_tr[(r0 + 8) * 65 + oc];
        float dv = s_tr[(r0 + 9) * 65 + oc];
        g_pool2pre[(size_t)(n0 + img) * 1024 + oc * 16 + py * 4 + px] =
            fmaxf(fmaxf(a, b), fmaxf(cv, dv));
    }
    __syncthreads();
    if (tid < 64) {
        g_ps2[blockIdx.x * 64 + tid] = s_psum[tid] + s_psum[64 + tid];
        g_pq2[blockIdx.x * 64 + tid] = s_psq[tid] + s_psq[64 + tid];
    }
}

// ================= fc1 via mma.sync: 128x64 tiles, K=1024 =================
__global__ void __launch_bounds__(256) k_fc1_mma(const float* __restrict__ bias) {
    __shared__ __align__(16) __nv_bfloat16 Ah[128 * 40];
    __shared__ __align__(16) __nv_bfloat16 Al[128 * 40];
    __shared__ __align__(16) __nv_bfloat16 Bs[32 * 72];
    __shared__ float s_sc[64], s_sh[64], s_al[64], s_bi[64];

    int tid = threadIdx.x, wid = tid >> 5, lid = tid & 31;
    int brow = blockIdx.y * 128, bcol = blockIdx.x * 64;
    if (tid < 64) {
        s_sc[tid] = g_bns2[tid]; s_sh[tid] = g_bnb2[tid];
        s_al[tid] = g_alphaf1[bcol + tid]; s_bi[tid] = bias[bcol + tid];
    }

    int wm = wid & 3, wn = wid >> 2;
    int rowoff8 = ((lid >> 3) & 1) * 8 + (lid & 7);
    int colb = (lid >= 16) ? 16 : 0;
    uint32_t sbAh = smem_u32(Ah), sbAl = smem_u32(Al), sbB = smem_u32(Bs);

    float acc[2][4][4] = {};

#pragma unroll 1
    for (int kc = 0; kc < 1024; kc += 32) {
        __syncthreads();
        for (int i = tid; i < 1024; i += 256) {
            int r = i >> 3, c4 = i & 7;
            int ch = (kc + c4 * 4) >> 4;
            float4 v = *(const float4*)&g_pool2pre[(size_t)(brow + r) * 1024 + kc + c4 * 4];
            float sc = s_sc[ch], sh = s_sh[ch];
            float f0 = fmaxf(v.x * sc + sh, 0.f);
            float f1 = fmaxf(v.y * sc + sh, 0.f);
            float f2 = fmaxf(v.z * sc + sh, 0.f);
            float f3 = fmaxf(v.w * sc + sh, 0.f);
            __nv_bfloat16 h0 = __float2bfloat16(f0), h1 = __float2bfloat16(f1);
            __nv_bfloat16 h2 = __float2bfloat16(f2), h3 = __float2bfloat16(f3);
            __nv_bfloat162* ph = (__nv_bfloat162*)&Ah[r * 40 + c4 * 4];
            __nv_bfloat162* pl = (__nv_bfloat162*)&Al[r * 40 + c4 * 4];
            ph[0] = __nv_bfloat162(h0, h1);
            ph[1] = __nv_bfloat162(h2, h3);
            pl[0] = __nv_bfloat162(__float2bfloat16(f0 - __bfloat162float(h0)),
                                   __float2bfloat16(f1 - __bfloat162float(h1)));
            pl[1] = __nv_bfloat162(__float2bfloat16(f2 - __bfloat162float(h2)),
                                   __float2bfloat16(f3 - __bfloat162float(h3)));
        }
        if (tid < 256) {
            int r = tid >> 3, c8 = tid & 7;
            *(uint4*)&Bs[r * 72 + c8 * 8] =
                *(const uint4*)&g_wf1bf[(size_t)(kc + r) * 512 + bcol + c8 * 8];
        }
        __syncthreads();
#pragma unroll
        for (int ks = 0; ks < 2; ks++) {
            uint32_t aH[2][4], aL[2][4], bu[2][4];
#pragma unroll
            for (int mh = 0; mh < 2; mh++) {
                uint32_t ra = (uint32_t)((wm * 32 + mh * 16 + rowoff8) * 80 + colb + ks * 32);
                ldsm_x4(aH[mh][0], aH[mh][1], aH[mh][2], aH[mh][3], sbAh + ra);
                ldsm_x4(aL[mh][0], aL[mh][1], aL[mh][2], aL[mh][3], sbAl + ra);
            }
#pragma unroll
            for (int nb = 0; nb < 2; nb++) {
                uint32_t rb = (uint32_t)((ks * 16 + rowoff8) * 144 + wn * 64 + nb * 32 + colb);
                ldsm_x4t(bu[nb][0], bu[nb][1], bu[nb][2], bu[nb][3], sbB + rb);
            }
#pragma unroll
            for (int mh = 0; mh < 2; mh++) {
                mma16816(acc[mh][0], aH[mh], bu[0][0], bu[0][1]);
                mma16816(acc[mh][1], aH[mh], bu[0][2], bu[0][3]);
                mma16816(acc[mh][2], aH[mh], bu[1][0], bu[1][1]);
                mma16816(acc[mh][3], aH[mh], bu[1][2], bu[1][3]);
                mma16816(acc[mh][0], aL[mh], bu[0][0], bu[0][1]);
                mma16816(acc[mh][1], aL[mh], bu[0][2], bu[0][3]);
                mma16816(acc[mh][2], aL[mh], bu[1][0], bu[1][1]);
                mma16816(acc[mh][3], aL[mh], bu[1][2], bu[1][3]);
            }
        }
    }
#pragma unroll
    for (int mh = 0; mh < 2; mh++) {
#pragma unroll
        for (int nb = 0; nb < 4; nb++) {
#pragma unroll
            for (int rp = 0; rp < 2; rp++) {
                int row = brow + wm * 32 + mh * 16 + (lid >> 2) + rp * 8;
                int cl = wn * 32 + nb * 8 + (lid & 3) * 2;
                float v0 = fmaxf(acc[mh][nb][rp * 2] * s_al[cl] + s_bi[cl], 0.f);
                float v1 = fmaxf(acc[mh][nb][rp * 2 + 1] * s_al[cl + 1] + s_bi[cl + 1], 0.f);
                *(float2*)&g_fc1o[(size_t)row * 512 + bcol + cl] = make_float2(v0, v1);
            }
        }
    }
}

// ================= fc2 =================
__global__ void __launch_bounds__(256) k_fc2(const float* __restrict__ bias,
                                             float* __restrict__ out) {
    __shared__ float s_w[5120];
    __shared__ float s_b[10];
    int tid = threadIdx.x;
    for (int i = tid; i < 5120; i += 256) s_w[i] = g_twf2[i];
    if (tid < 10) s_b[tid] = bias[tid];
    __syncthreads();
    int wid = tid >> 5, lane = tid & 31;
    int img = blockIdx.x * 8 + wid;
    const float* xr = g_fc1o + (size_t)img * 512;
    float acc[10];
#pragma unroll
    for (int j = 0; j < 10; j++) acc[j] = 0.f;
    for (int k = lane; k < 512; k += 32) {
        float xv = xr[k];
#pragma unroll
        for (int j = 0; j < 10; j++) acc[j] += xv * s_w[j * 512 + k];
    }
#pragma unroll
    for (int j = 0; j < 10; j++)
        for (int o = 16; o; o >>= 1) acc[j] += __shfl_xor_sync(0xffffffffu, acc[j], o);
    if (lane == 0) {
#pragma unroll
        for (int j = 0; j < 10; j++) out[(size_t)img * 10 + j] = acc[j] + s_b[j];
    }
}

// ================= launch =================
extern "C" void kernel_launch(void* const* d_in, const int* in_sizes, int n_in,
                              void* d_out, int out_size) {
    const float* x   = (const float*)d_in[0];
    const float* w1  = (const float*)d_in[1];
    const float* b1  = (const float*)d_in[2];
    const float* ga1 = (const float*)d_in[3];
    const float* be1 = (const float*)d_in[4];
    const float* w2  = (const float*)d_in[5];
    const float* b2  = (const float*)d_in[6];
    const float* ga2 = (const float*)d_in[7];
    const float* be2 = (const float*)d_in[8];
    const float* wf1 = (const float*)d_in[9];
    const float* bf1 = (const float*)d_in[10];
    const float* wf2 = (const float*)d_in[11];
    const float* bf2 = (const float*)d_in[12];
    float* out = (float*)d_out;

    cudaFuncSetAttribute(k_conv1_mma, cudaFuncAttributeMaxDynamicSharedMemorySize, SMEM1);
    cudaFuncSetAttribute(k_conv2_mma, cudaFuncAttributeMaxDynamicSharedMemorySize, SMEM_MMA);

    k_ternarize_all<<<618, 256>>>(w1, w2, wf1, wf2);
    k_prepw2<<<200, 256>>>();
    k_prepwf1<<<2048, 256>>>();
    k_conv1_mma<<<NB, 288, SMEM1>>>(x, b1);
    k_bnstats<<<32, 256>>>(1, ga1, be1);
    k_conv2_mma<<<NB / 2, 256, SMEM_MMA>>>(b2);
    k_bnstats<<<64, 256>>>(2, ga2, be2);
    k_fc1_mma<<<dim3(512 / 64, NB / 128), 256>>>(bf1);
    k_fc2<<<NB / 8, 256>>>(bf2, out);
}